// round 9
// baseline (speedup 1.0000x reference)
#include <cuda_runtime.h>
#include <cstddef>

// Shapes fixed by the problem definition.
#define BB 32
#define FF 128
#define TT 8192

// Per output-time-index j: {wy_j, bitcast(y0_j)}. 16B-aligned for float4 loads.
__device__ __align__(16) float2 g_tab[TT];

// ---------------------------------------------------------------------------
// Kernel 1: per-j warp table (depends on source_pt / dest_pt device scalars).
// Faithful fp32 math (__fdiv_rn) matching the JAX reference.
// ---------------------------------------------------------------------------
__global__ void __launch_bounds__(256) k_tab(const int* __restrict__ src_p,
                                             const int* __restrict__ dst_p) {
    int j = blockIdx.x * 256 + threadIdx.x;
    if (j >= TT) return;
    float srcf = (float)(*src_p);
    float dstf = (float)(*dst_p);
    float lr = __fdiv_rn(dstf, srcf);                                 // dest/source
    float rr = __fdiv_rn((float)TT - dstf, (float)TT - srcf);         // (T-dest)/(T-source)

    float t   = (float)j;
    float ind = (t < dstf) ? __fdiv_rn(t, lr)
                           : (srcf + __fdiv_rn(t - dstf, rr));
    ind = fminf(fmaxf(ind, 0.0f), (float)(TT - 1));

    float ypix = __fdiv_rn(ind, (float)(TT - 1)) * (float)(FF - 1);
    ypix = fminf(fmaxf(ypix, 0.0f), (float)(FF - 1));
    float yf = floorf(ypix);
    int   y0 = (int)yf;
    float wy = ypix - yf;
    g_tab[j] = make_float2(wy, __int_as_float(y0));
}

// ---------------------------------------------------------------------------
// Kernel 2 (fused): one block per (b,i) output row.
// Prologue: gather the two input columns x0(i), x1(i) across the 128 freq
// rows (128 threads x 2 scattered LDGs), build the lerped A-column and its
// forward diff D in shared memory (D[127]=0 absorbs the y1 clamp).
// Main loop: stream 8192 outputs as 8 x float4 per thread:
//   out[j] = fma(wy_j, sD[y0_j], sA[y0_j])
// Stores use __stcs (evict-first) — pure write stream, keep L2 for the
// table + gather data.
// ---------------------------------------------------------------------------
__global__ void __launch_bounds__(256) k_fused(const float* __restrict__ S,
                                               float* __restrict__ out) {
    __shared__ float sA[FF];
    __shared__ float sD[FF];

    int row = blockIdx.x;            // b*128 + i
    int tid = threadIdx.x;
    int i   = row & (FF - 1);
    int b   = row >> 7;

    if (tid < FF) {
        // x_pix = i/(F-1)*(T-1), clip, floor — faithful fp32 math.
        float xpix = __fdiv_rn((float)i, (float)(FF - 1)) * (float)(TT - 1);
        xpix = fminf(fmaxf(xpix, 0.0f), (float)(TT - 1));
        float xf = floorf(xpix);
        int   x0 = (int)xf;
        int   x1 = min(x0 + 1, TT - 1);
        float wx = xpix - xf;

        const float* Sr = S + ((size_t)b * FF + tid) * TT;   // freq row = tid
        float s0 = __ldg(Sr + x0);
        float s1 = __ldg(Sr + x1);
        sA[tid] = fmaf(wx, s1 - s0, s0);                     // (1-wx)*s0 + wx*s1
    }
    __syncthreads();
    if (tid < FF) {
        sD[tid] = (tid < FF - 1) ? (sA[tid + 1] - sA[tid]) : 0.0f;
    }
    __syncthreads();

    const float4* tab4 = (const float4*)g_tab;               // 2 j-entries per float4
    float4* orow = (float4*)(out + (size_t)row * TT);        // 2048 float4 groups

#pragma unroll
    for (int k = 0; k < 8; k++) {
        int jg = k * 256 + tid;                              // group index 0..2047
        float4 t01 = __ldg(&tab4[jg * 2]);                   // {wy0, y0, wy1, y1}
        float4 t23 = __ldg(&tab4[jg * 2 + 1]);               // {wy2, y2, wy3, y3}
        int o0 = __float_as_int(t01.y);
        int o1 = __float_as_int(t01.w);
        int o2 = __float_as_int(t23.y);
        int o3 = __float_as_int(t23.w);
        float4 o;
        o.x = fmaf(t01.x, sD[o0], sA[o0]);
        o.y = fmaf(t01.z, sD[o1], sA[o1]);
        o.z = fmaf(t23.x, sD[o2], sA[o2]);
        o.w = fmaf(t23.z, sD[o3], sA[o3]);
        __stcs(&orow[jg], o);
    }
}

// ---------------------------------------------------------------------------
extern "C" void kernel_launch(void* const* d_in, const int* in_sizes, int n_in,
                              void* d_out, int out_size) {
    const float* S   = (const float*)d_in[0];
    const int*   src = (const int*)d_in[1];
    const int*   dst = (const int*)d_in[2];
    float*       out = (float*)d_out;
    (void)in_sizes; (void)n_in; (void)out_size;

    k_tab<<<(TT + 255) / 256, 256>>>(src, dst);
    k_fused<<<BB * FF, 256>>>(S, out);
}

// round 13
// speedup vs baseline: 1.5710x; 1.5710x over previous
#include <cuda_runtime.h>
#include <cstddef>

// Shapes fixed by the problem definition.
#define BB 32
#define FF 128
#define TT 8192

// Warp-table constants: {sl_l, sl_r, c_r, dstf}
//   t <  dstf : ind = t * sl_l                (sl_l = 1/lr, lr = dst/src)
//   t >= dstf : ind = fma(t, sl_r, c_r)       (sl_r = 1/rr, c_r = src - dst*sl_r)
__device__ float4 g_c;

__global__ void k_const(const int* __restrict__ src_p,
                        const int* __restrict__ dst_p) {
    float sf = (float)(*src_p);
    float df = (float)(*dst_p);
    float lr = __fdiv_rn(df, sf);                                  // dest/source
    float rr = __fdiv_rn((float)TT - df, (float)TT - sf);          // (T-dest)/(T-source)
    float sl_l = __fdiv_rn(1.0f, lr);
    float sl_r = __fdiv_rn(1.0f, rr);
    float c_r  = sf - df * sl_r;
    g_c = make_float4(sl_l, sl_r, c_r, df);
}

// ---------------------------------------------------------------------------
// Fused kernel: one block per (b,i) output row, 256 threads.
//
// Prologue: all 256 threads gather the two input columns x0(i), x1(i) across
// the 128 freq rows in parallel, build the x-lerped column A and its forward
// diff D, interleaved as float2 sAD[r] = {A[r], A[r+1]-A[r]} (D[127]=0 absorbs
// the y1 clamp).
//
// Main loop: 8 x float4 per thread. y0/wy are computed in registers from the
// piecewise-linear warp map (no table memory traffic). The 4 consecutive j's
// in a group almost always share y0, so the A/D fetch is 1 broadcast LDS.64
// plus 3 predicated (mostly inactive) LDS.64.
//   out[j] = fma(wy_j, D[y0_j], A[y0_j])
// ---------------------------------------------------------------------------
__global__ void __launch_bounds__(256) k_fused(const float* __restrict__ S,
                                               float* __restrict__ out) {
    __shared__ float2 sAD[FF];
    __shared__ float  sTmp[FF];

    int row = blockIdx.x;            // b*128 + i
    int tid = threadIdx.x;
    int i   = row & (FF - 1);
    int b   = row >> 7;

    // x_pix = i/(F-1)*(T-1), clip, floor — faithful fp32 math.
    float xpix = __fdiv_rn((float)i, (float)(FF - 1)) * (float)(TT - 1);
    xpix = fminf(fmaxf(xpix, 0.0f), (float)(TT - 1));
    float xf = floorf(xpix);
    int   x0 = (int)xf;
    int   x1 = min(x0 + 1, TT - 1);
    float wx = xpix - xf;

    // Parallel gather: threads 0-127 fetch column x0, threads 128-255 column x1.
    if (tid < FF) {
        sAD[tid].x = __ldg(S + ((size_t)b * FF + tid) * TT + x0);
    } else {
        sAD[tid - FF].y = __ldg(S + ((size_t)b * FF + (tid - FF)) * TT + x1);
    }
    __syncthreads();
    if (tid < FF) {
        float2 v = sAD[tid];
        sTmp[tid] = fmaf(wx, v.y - v.x, v.x);      // A[r] = (1-wx)*s0 + wx*s1
    }
    __syncthreads();
    if (tid < FF) {
        float a = sTmp[tid];
        sAD[tid] = make_float2(a, (tid < FF - 1) ? (sTmp[tid + 1] - a) : 0.0f);
    }
    __syncthreads();

    float4 C = g_c;                                 // L1/L2-hot 16B load
    const float sl_l = C.x, sl_r = C.y, c_r = C.z, dstf = C.w;
    const float inv_t1 = 1.0f / (float)(TT - 1);    // compile-time rn constant

    float4* orow = (float4*)(out + (size_t)row * TT);

#pragma unroll
    for (int k = 0; k < 8; k++) {
        int   jg    = k * 256 + tid;                // float4 group, 0..2047
        float tbase = (float)(jg * 4);

        int   oi[4];
        float wyv[4];
#pragma unroll
        for (int e = 0; e < 4; e++) {
            float t  = tbase + (float)e;
            float ia = t * sl_l;
            float ib = fmaf(t, sl_r, c_r);
            float ind = (t < dstf) ? ia : ib;
            ind = fminf(fmaxf(ind, 0.0f), (float)(TT - 1));
            float yp = (ind * inv_t1) * (float)(FF - 1);
            yp = fminf(yp, (float)(FF - 1));        // guard rounding past 127.0
            float yf = floorf(yp);
            oi[e]  = (int)yf;
            wyv[e] = yp - yf;
        }

        float2 ad0 = sAD[oi[0]];
        float2 ad1 = (oi[1] == oi[0]) ? ad0 : sAD[oi[1]];
        float2 ad2 = (oi[2] == oi[0]) ? ad0 : sAD[oi[2]];
        float2 ad3 = (oi[3] == oi[0]) ? ad0 : sAD[oi[3]];

        float4 o;
        o.x = fmaf(wyv[0], ad0.y, ad0.x);
        o.y = fmaf(wyv[1], ad1.y, ad1.x);
        o.z = fmaf(wyv[2], ad2.y, ad2.x);
        o.w = fmaf(wyv[3], ad3.y, ad3.x);
        __stcs(&orow[jg], o);
    }
}

// ---------------------------------------------------------------------------
extern "C" void kernel_launch(void* const* d_in, const int* in_sizes, int n_in,
                              void* d_out, int out_size) {
    const float* S   = (const float*)d_in[0];
    const int*   src = (const int*)d_in[1];
    const int*   dst = (const int*)d_in[2];
    float*       out = (float*)d_out;
    (void)in_sizes; (void)n_in; (void)out_size;

    k_const<<<1, 1>>>(src, dst);
    k_fused<<<BB * FF, 256>>>(S, out);
}